// round 2
// baseline (speedup 1.0000x reference)
#include <cuda_runtime.h>
#include <cuda_bf16.h>

#define THREADS 256
#define TILE_EDGES 64
#define XPITCH 132   // fp32 elems per staged edge row (pad: 132 mod 32 = 4 banks/row)
#define WPITCH 72    // bf16 elems per W row (144B: +4 banks/row)

__device__ int g_idx_is64;

// ---------------- zero output ----------------
__global__ void zero_out_kernel(float4* out, int n4) {
    int i = blockIdx.x * blockDim.x + threadIdx.x;
    int stride = gridDim.x * blockDim.x;
    for (; i < n4; i += stride) out[i] = make_float4(0.f, 0.f, 0.f, 0.f);
}

// ---------------- detect index dtype (int64 vs int32) ----------------
// If int64 (values < 50000, nonneg), every odd 32-bit word is 0.
// If int32, odd words are random node ids -> virtually surely nonzero.
__global__ void detect_idx_kernel(const unsigned int* w, int n_pairs) {
    __shared__ unsigned int acc;
    if (threadIdx.x == 0) acc = 0u;
    __syncthreads();
    unsigned int v = 0u;
    for (int i = threadIdx.x; i < n_pairs; i += blockDim.x) v |= w[2 * i + 1];
    atomicOr(&acc, v);
    __syncthreads();
    if (threadIdx.x == 0) g_idx_is64 = (acc == 0u) ? 1 : 0;
}

static __device__ __forceinline__ unsigned int pack_bf16x2(float lo, float hi) {
    __nv_bfloat162 h = __float22bfloat162_rn(make_float2(lo, hi));
    return *reinterpret_cast<unsigned int*>(&h);
}

// ---------------- fused gate-GEMM + scatter ----------------
__global__ __launch_bounds__(THREADS, 2)
void fused_gate_scatter(const float* __restrict__ x,
                        const float* __restrict__ Wg,
                        const float* __restrict__ lparam,
                        const void* __restrict__ index,
                        float* __restrict__ out,
                        long long E, int num_tiles)
{
    extern __shared__ char smem_raw[];
    float* Xsm = reinterpret_cast<float*>(smem_raw);                     // [64][XPITCH] fp32
    __nv_bfloat16* Wsm =
        reinterpret_cast<__nv_bfloat16*>(smem_raw + TILE_EDGES * XPITCH * 4); // [128][WPITCH]

    const int tid  = threadIdx.x;
    const int wid  = tid >> 5;
    const int lane = tid & 31;
    const int g    = lane >> 2;   // group id 0..7  (row within warp tile)
    const int q    = lane & 3;    // quad   0..3

    const int   is64 = g_idx_is64;
    const float lp   = fabsf(__ldg(lparam));

    // Stage W [128 out][64 k] fp32 -> bf16 smem, pitch WPITCH
    for (int i = tid; i < 128 * 32; i += THREADS) {
        int o  = i >> 5;
        int kh = i & 31;                     // float2 index -> k = 2*kh
        float2 wv = __ldg(reinterpret_cast<const float2*>(Wg) + o * 32 + kh);
        unsigned int pk = pack_bf16x2(wv.x, wv.y);
        *reinterpret_cast<unsigned int*>(&Wsm[o * WPITCH + 2 * kh]) = pk;
    }
    // (first __syncthreads inside the loop orders W writes before any read)

    for (int tile = blockIdx.x; tile < num_tiles; tile += (int)gridDim.x) {
        const long long ebase = (long long)tile * TILE_EDGES;

        // ---- stage X tile: 64 edges x 128 fp32, float4 coalesced ----
        #pragma unroll
        for (int p = 0; p < 8; p++) {
            int i  = tid + p * THREADS;      // 0..2047
            int el = i >> 5;                 // local edge
            int jq = i & 31;                 // float4 index within row
            long long e = ebase + el;
            float4 v = make_float4(0.f, 0.f, 0.f, 0.f);
            if (e < E) v = __ldg(reinterpret_cast<const float4*>(x + e * 128) + jq);
            *reinterpret_cast<float4*>(&Xsm[el * XPITCH + jq * 4]) = v;
        }
        __syncthreads();

        // ---- per-warp MMA over 8 edges: rows 0..7 = patch0, 8..15 = patch1 ----
        const int erow = wid * 8 + g;                 // this thread's edge (local)
        const long long eg = ebase + erow;
        const bool valid = (eg < E);
        long long node = 0;
        if (valid) {
            node = is64 ? reinterpret_cast<const long long*>(index)[eg]
                        : (long long)reinterpret_cast<const int*>(index)[eg];
        }

        float acc[16][4];
        #pragma unroll
        for (int nt = 0; nt < 16; nt++) {
            acc[nt][0] = 0.f; acc[nt][1] = 0.f; acc[nt][2] = 0.f; acc[nt][3] = 0.f;
        }

        const float* Xrow = &Xsm[erow * XPITCH];

        #pragma unroll
        for (int ks = 0; ks < 4; ks++) {
            const int kb = ks * 16 + q * 2;
            // A fragment: reg0 = (row g,  k kb..kb+1) = patch0
            //             reg1 = (row g+8, kb..kb+1)  = patch1
            //             reg2 = (row g,  kb+8..+9), reg3 = (row g+8, kb+8..+9)
            float2 f0 = *reinterpret_cast<const float2*>(Xrow + kb);
            float2 f1 = *reinterpret_cast<const float2*>(Xrow + 64 + kb);
            float2 f2 = *reinterpret_cast<const float2*>(Xrow + kb + 8);
            float2 f3 = *reinterpret_cast<const float2*>(Xrow + 64 + kb + 8);
            unsigned int a0 = pack_bf16x2(f0.x, f0.y);
            unsigned int a1 = pack_bf16x2(f1.x, f1.y);
            unsigned int a2 = pack_bf16x2(f2.x, f2.y);
            unsigned int a3 = pack_bf16x2(f3.x, f3.y);

            #pragma unroll
            for (int nt = 0; nt < 16; nt++) {
                const int n = nt * 8 + g;             // gate output index (B col)
                const __nv_bfloat16* wrow = &Wsm[n * WPITCH + kb];
                unsigned int b0 = *reinterpret_cast<const unsigned int*>(wrow);
                unsigned int b1 = *reinterpret_cast<const unsigned int*>(wrow + 8);
                asm volatile(
                    "mma.sync.aligned.m16n8k16.row.col.f32.bf16.bf16.f32 "
                    "{%0,%1,%2,%3}, {%4,%5,%6,%7}, {%8,%9}, {%0,%1,%2,%3};"
                    : "+f"(acc[nt][0]), "+f"(acc[nt][1]),
                      "+f"(acc[nt][2]), "+f"(acc[nt][3])
                    : "r"(a0), "r"(a1), "r"(a2), "r"(a3), "r"(b0), "r"(b1));
            }
        }

        // ---- epilogue: clamp, recombine with fp32 e1, fused dual-scatter ----
        const float* Xp0 = Xrow;
        const float* Xp1 = Xrow + 64;
        float* obase = out + node * 128;
        #pragma unroll
        for (int nt = 0; nt < 16; nt++) {
            const int o   = nt * 8 + q * 2;   // gate/output column (c0,c1 at o,o+1)
            const int dlo = o & 63;
            float c0 = __saturatef(acc[nt][0]);   // (edge, p0, o)
            float c1 = __saturatef(acc[nt][1]);   // (edge, p0, o+1)
            float c2 = __saturatef(acc[nt][2]);   // (edge, p1, o)
            float c3 = __saturatef(acc[nt][3]);   // (edge, p1, o+1)
            float2 e0 = *reinterpret_cast<const float2*>(Xp0 + dlo);  // e1[edge,0,dlo..]
            float2 e1 = *reinterpret_cast<const float2*>(Xp1 + dlo);  // e1[edge,1,dlo..]
            float outx = e0.x * c0 + e1.x * c2;
            float outy = e0.y * c1 + e1.y * c3;
            // pass-through e term (fp32-exact): e[edge,o] = e1[edge, o/64, o%64]
            float evx = (nt >= 8) ? e1.x : e0.x;
            float evy = (nt >= 8) ? e1.y : e0.y;
            float vx = fmaf(lp, outx, evx);
            float vy = fmaf(lp, outy, evy);
            if (valid) {
                float* p = obase + o;
                asm volatile("red.global.add.v2.f32 [%0], {%1, %2};"
                             :: "l"(p), "f"(vx), "f"(vy) : "memory");
            }
        }
        __syncthreads();   // Xsm reused next tile
    }
}

// ---------------- launch ----------------
extern "C" void kernel_launch(void* const* d_in, const int* in_sizes, int n_in,
                              void* d_out, int out_size) {
    const float* x  = (const float*)d_in[0];
    const float* Wg = (const float*)d_in[1];
    const float* lp = (const float*)d_in[2];
    const void*  idx = d_in[3];
    float* out = (float*)d_out;

    long long E = (long long)in_sizes[0] / 128;
    int tiles = (int)((E + TILE_EDGES - 1) / TILE_EDGES);

    int dev = 0; cudaGetDevice(&dev);
    int sms = 148;
    cudaDeviceGetAttribute(&sms, cudaDevAttrMultiProcessorCount, dev);

    // zero output (poisoned to 0xAA by harness)
    int n4 = out_size / 4;
    int zgrid = (n4 + THREADS - 1) / THREADS;
    zero_out_kernel<<<zgrid, THREADS>>>((float4*)d_out, n4);

    // detect index dtype
    int npairs = (int)(E / 2); if (npairs > 4096) npairs = 4096;
    detect_idx_kernel<<<1, 256>>>((const unsigned int*)idx, npairs);

    size_t smem = (size_t)TILE_EDGES * XPITCH * 4 + (size_t)128 * WPITCH * 2;
    cudaFuncSetAttribute(fused_gate_scatter,
                         cudaFuncAttributeMaxDynamicSharedMemorySize, (int)smem);
    int grid = sms * 2;
    if (grid > tiles) grid = tiles;
    fused_gate_scatter<<<grid, THREADS, smem>>>(x, Wg, lp, idx, out, E, tiles);
}